// round 9
// baseline (speedup 1.0000x reference)
#include <cuda_runtime.h>
#include <math.h>
#include <stdint.h>

// ---------------------------------------------------------------------------
// HE_ColorNormalization, SMEM-resident persistent NMF (diagnostic reorder).
//   d_in[0] pic float32 (3,1024,1024) | d_in[1] W_target (3,4) | d_in[2] Ht_RM ()
//   d_in[3] W0 (N,4) | d_in[4] H0 (3,4)    Output: float32 (3,1024,1024)
// 148 CTAs x 512 thr, 1 CTA/SM; Wc (113KB) + V (85KB) live in dynamic smem.
// k_loop is the 4th launch so the ncu -s5-c1 capture lands on it.
// ---------------------------------------------------------------------------

#define N_PIX    1048576
#define N_ITERS  100
#define EPSF     1e-8f
#define GRID     148
#define NTHR     512
#define PPC      7086                    // ceil(N_PIX / GRID)
#define KMAX     14                      // ceil(PPC / NTHR)
#define TOTAL    (4 * N_PIX)
#define RANK0    4152359u                // floor(0.99*(TOTAL-1))
#define RANK1    4152360u
#define HREP     16
#define SMEM_BYTES (PPC * 16 + 3 * PPC * 4)   // 198408 bytes

typedef unsigned long long u64;

__device__ __forceinline__ u64 pk2(float lo, float hi) {
    u64 r; asm("mov.b64 %0, {%1, %2};" : "=l"(r) : "f"(lo), "f"(hi)); return r;
}
__device__ __forceinline__ void upk2(u64 v, float& lo, float& hi) {
    asm("mov.b64 {%0, %1}, %2;" : "=f"(lo), "=f"(hi) : "l"(v));
}
__device__ __forceinline__ u64 fma2_(u64 a, u64 b, u64 c) {
    u64 d; asm("fma.rn.f32x2 %0, %1, %2, %3;" : "=l"(d) : "l"(a), "l"(b), "l"(c)); return d;
}
__device__ __forceinline__ u64 mul2_(u64 a, u64 b) {
    u64 d; asm("mul.rn.f32x2 %0, %1, %2;" : "=l"(d) : "l"(a), "l"(b)); return d;
}

// Scratch (static device globals: no allocation allowed)
__device__ float4   g_Wc[N_PIX];
__device__ float    g_part[2][22][GRID];
__device__ unsigned g_arrive;
__device__ unsigned g_hist1[HREP * 65536];
__device__ unsigned g_hist2a[65536];
__device__ unsigned g_hist2b[65536];
__device__ unsigned g_bA, g_bB, g_cumA, g_cumB;
__device__ float    g_scale;

__device__ __forceinline__ float od_clip(float x) {
    x = fminf(fmaxf(x, 0.01f), 0.99f);
    return -__logf(x);
}

// --------------------------------------------------------------------------
// init split into 3 launches so k_loop is launch #4 (ncu capture slot).
// --------------------------------------------------------------------------
__global__ void k_init_a() {
    int i = blockIdx.x * blockDim.x + threadIdx.x;
    int stride = gridDim.x * blockDim.x;
    uint4 z = make_uint4(0u, 0u, 0u, 0u);
    uint4* h1 = (uint4*)g_hist1;
    for (int h = i; h < HREP * 65536 / 4; h += stride) h1[h] = z;
}
__global__ void k_init_b() {
    int i = blockIdx.x * blockDim.x + threadIdx.x;
    int stride = gridDim.x * blockDim.x;
    uint4 z = make_uint4(0u, 0u, 0u, 0u);
    uint4* h2a = (uint4*)g_hist2a;
    uint4* h2b = (uint4*)g_hist2b;
    for (int h = i; h < 65536 / 4; h += stride) { h2a[h] = z; h2b[h] = z; }
}
__global__ void k_init_c() {
    if (threadIdx.x == 0 && blockIdx.x == 0) g_arrive = 0u;
}

// --------------------------------------------------------------------------
__global__ __launch_bounds__(NTHR, 1) void k_loop(const float* __restrict__ pic,
                                                  const float* __restrict__ W0,
                                                  const float* __restrict__ H0) {
    extern __shared__ float smem_dyn[];
    float4* swc = (float4*)smem_dyn;          // [PPC]
    float*  sv0 = (float*)(swc + PPC);
    float*  sv1 = sv0 + PPC;
    float*  sv2 = sv1 + PPC;

    __shared__ float sHd[12];
    __shared__ float red[NTHR / 32][22];
    __shared__ float tot[22];

    const int tid  = threadIdx.x;
    const int cta  = blockIdx.x;
    const int warp = tid >> 5, lane = tid & 31;
    const int base = cta * PPC;

    if (tid < 12) sHd[tid] = H0[tid];

    const float4* w04 = (const float4*)W0;
    for (int l = tid; l < PPC; l += NTHR) {
        int p = base + l;
        if (p < N_PIX) {
            swc[l] = w04[p];
            sv0[l] = od_clip(pic[p]);
            sv1[l] = od_clip(pic[N_PIX + p]);
            sv2[l] = od_clip(pic[2 * N_PIX + p]);
        }
    }
    __syncthreads();

    unsigned* hist = &g_hist1[(cta & (HREP - 1)) * 65536];

    for (int iter = 0; iter < N_ITERS; iter++) {
        float hd[12];
#pragma unroll
        for (int t = 0; t < 12; t++) hd[t] = sHd[t];

        float G[16];
#pragma unroll
        for (int k = 0; k < 4; k++)
#pragma unroll
            for (int j = 0; j < 4; j++)
                G[k*4+j] = hd[k]*hd[j] + hd[4+k]*hd[4+j] + hd[8+k]*hd[8+j];

        u64 hd2[3][2], G2[4][2];
#pragma unroll
        for (int c = 0; c < 3; c++) {
            hd2[c][0] = pk2(hd[c*4+0], hd[c*4+1]);
            hd2[c][1] = pk2(hd[c*4+2], hd[c*4+3]);
        }
#pragma unroll
        for (int k = 0; k < 4; k++) {
            G2[k][0] = pk2(G[k*4+0], G[k*4+1]);
            G2[k][1] = pk2(G[k*4+2], G[k*4+3]);
        }
        const u64 eps2 = pk2(EPSF, EPSF);

        u64 aA[3][2], aB[4][2];
#pragma unroll
        for (int c = 0; c < 3; c++) { aA[c][0] = 0ull; aA[c][1] = 0ull; }
#pragma unroll
        for (int j = 0; j < 4; j++) { aB[j][0] = 0ull; aB[j][1] = 0ull; }

        const bool last = (iter == N_ITERS - 1);

#pragma unroll
        for (int k = 0; k < KMAX; k++) {
            int l = tid + k * NTHR;
            int p = base + l;
            if (l >= PPC || p >= N_PIX) continue;

            float v0 = sv0[l], v1 = sv1[l], v2 = sv2[l];
            float4 w = swc[l];

            u64 vb0 = pk2(v0, v0), vb1 = pk2(v1, v1), vb2 = pk2(v2, v2);
            u64 n0 = fma2_(vb0, hd2[0][0], fma2_(vb1, hd2[1][0], mul2_(vb2, hd2[2][0])));
            u64 n1 = fma2_(vb0, hd2[0][1], fma2_(vb1, hd2[1][1], mul2_(vb2, hd2[2][1])));

            u64 wb0 = pk2(w.x, w.x), wb1 = pk2(w.y, w.y);
            u64 wb2 = pk2(w.z, w.z), wb3 = pk2(w.w, w.w);
            u64 d0 = fma2_(wb0, G2[0][0], fma2_(wb1, G2[1][0],
                     fma2_(wb2, G2[2][0], fma2_(wb3, G2[3][0], eps2))));
            u64 d1 = fma2_(wb0, G2[0][1], fma2_(wb1, G2[1][1],
                     fma2_(wb2, G2[2][1], fma2_(wb3, G2[3][1], eps2))));

            float num0, num1, num2, num3, den0, den1, den2, den3;
            upk2(n0, num0, num1); upk2(n1, num2, num3);
            upk2(d0, den0, den1); upk2(d1, den2, den3);

            float nw0 = w.x * __fdividef(num0, den0);
            float nw1 = w.y * __fdividef(num1, den1);
            float nw2 = w.z * __fdividef(num2, den2);
            float nw3 = w.w * __fdividef(num3, den3);
            swc[l] = make_float4(nw0, nw1, nw2, nw3);

            u64 nwp0 = pk2(nw0, nw1), nwp1 = pk2(nw2, nw3);
            aA[0][0] = fma2_(vb0, nwp0, aA[0][0]); aA[0][1] = fma2_(vb0, nwp1, aA[0][1]);
            aA[1][0] = fma2_(vb1, nwp0, aA[1][0]); aA[1][1] = fma2_(vb1, nwp1, aA[1][1]);
            aA[2][0] = fma2_(vb2, nwp0, aA[2][0]); aA[2][1] = fma2_(vb2, nwp1, aA[2][1]);

            u64 nb0 = pk2(nw0, nw0), nb1 = pk2(nw1, nw1);
            u64 nb2 = pk2(nw2, nw2), nb3 = pk2(nw3, nw3);
            aB[0][0] = fma2_(nb0, nwp0, aB[0][0]); aB[0][1] = fma2_(nb0, nwp1, aB[0][1]);
            aB[1][0] = fma2_(nb1, nwp0, aB[1][0]); aB[1][1] = fma2_(nb1, nwp1, aB[1][1]);
            aB[2][0] = fma2_(nb2, nwp0, aB[2][0]); aB[2][1] = fma2_(nb2, nwp1, aB[2][1]);
            aB[3][0] = fma2_(nb3, nwp0, aB[3][0]); aB[3][1] = fma2_(nb3, nwp1, aB[3][1]);

            if (last) {
                g_Wc[p] = make_float4(nw0, nw1, nw2, nw3);
                atomicAdd(&hist[__float_as_uint(nw0) >> 16], 1u);
                atomicAdd(&hist[__float_as_uint(nw1) >> 16], 1u);
                atomicAdd(&hist[__float_as_uint(nw2) >> 16], 1u);
                atomicAdd(&hist[__float_as_uint(nw3) >> 16], 1u);
            }
        }

        if (last) break;

        float acc[22];
        upk2(aA[0][0], acc[0],  acc[1]);  upk2(aA[0][1], acc[2],  acc[3]);
        upk2(aA[1][0], acc[4],  acc[5]);  upk2(aA[1][1], acc[6],  acc[7]);
        upk2(aA[2][0], acc[8],  acc[9]);  upk2(aA[2][1], acc[10], acc[11]);
        {
            float B00,B01,B02,B03,B11,B12,B13,B22,B23,B33, t0, t1;
            upk2(aB[0][0],B00,B01); upk2(aB[0][1],B02,B03);
            upk2(aB[1][0],t0, B11); upk2(aB[1][1],B12,B13);
            upk2(aB[2][0],t0, t1 ); upk2(aB[2][1],B22,B23);
            upk2(aB[3][1],t0, B33);
            acc[12]=B00; acc[13]=B01; acc[14]=B02; acc[15]=B03;
            acc[16]=B11; acc[17]=B12; acc[18]=B13;
            acc[19]=B22; acc[20]=B23; acc[21]=B33;
        }

#pragma unroll
        for (int t = 0; t < 22; t++)
#pragma unroll
            for (int off = 16; off > 0; off >>= 1)
                acc[t] += __shfl_down_sync(0xFFFFFFFFu, acc[t], off);
        if (lane == 0) {
#pragma unroll
            for (int t = 0; t < 22; t++) red[warp][t] = acc[t];
        }
        __syncthreads();
        if (tid < 22) {
            float s = 0.0f;
#pragma unroll
            for (int w = 0; w < NTHR / 32; w++) s += red[w][tid];
            g_part[iter & 1][tid][cta] = s;
        }
        __syncthreads();

        // grid barrier: release-arrive + acquire-spin (no trailing membar)
        if (tid == 0) {
            __threadfence();
            asm volatile("red.release.gpu.global.add.u32 [%0], %1;"
                         :: "l"(&g_arrive), "r"(1u) : "memory");
            const unsigned target = (unsigned)(iter + 1) * (unsigned)GRID;
            unsigned cur;
            do {
                asm volatile("ld.acquire.gpu.global.u32 %0, [%1];"
                             : "=r"(cur) : "l"(&g_arrive) : "memory");
                if (cur >= target) break;
                __nanosleep(32);
            } while (true);
        }
        __syncthreads();

        // all CTAs reduce partials in fixed order (deterministic)
        for (int v = warp; v < 22; v += NTHR / 32) {
            float s = 0.0f;
            for (int b = lane; b < GRID; b += 32) s += g_part[iter & 1][v][b];
#pragma unroll
            for (int off = 16; off > 0; off >>= 1)
                s += __shfl_down_sync(0xFFFFFFFFu, s, off);
            if (lane == 0) tot[v] = s;
        }
        __syncthreads();

        // parallel Hd update: 12 threads, one output element each
        if (tid < 12) {
            int c = tid >> 2, j = tid & 3;
            float den = EPSF;
#pragma unroll
            for (int k = 0; k < 4; k++) {
                int a = k < j ? k : j;
                int b = k < j ? j : k;
                int idx = a * 4 - ((a * (a + 1)) >> 1) + b;   // sym(4) packed index
                den += hd[c * 4 + k] * tot[12 + idx];
            }
            sHd[tid] = hd[tid] * __fdividef(tot[c * 4 + j], den);
        }
        __syncthreads();
    }
}

// ---------------------------------------------------------------------------
__global__ void k_sel1() {
    __shared__ unsigned chunk[1024];
    int tid = threadIdx.x;
    unsigned s = 0;
    for (int k = 0; k < 64; k++) {
        unsigned bin = tid * 64 + k;
        unsigned c = 0;
#pragma unroll
        for (int r = 0; r < HREP; r++) c += g_hist1[r * 65536 + bin];
        s += c;
    }
    chunk[tid] = s;
    __syncthreads();
    if (tid == 0) {
        unsigned run = 0;
        for (int i = 0; i < 1024; i++) { unsigned c = chunk[i]; chunk[i] = run; run += c; }
    }
    __syncthreads();
    unsigned c = chunk[tid];
    for (int k = 0; k < 64; k++) {
        unsigned bin = tid * 64 + k;
        unsigned h = 0;
#pragma unroll
        for (int r = 0; r < HREP; r++) h += g_hist1[r * 65536 + bin];
        if (RANK0 >= c && RANK0 < c + h) { g_bA = bin; g_cumA = c; }
        if (RANK1 >= c && RANK1 < c + h) { g_bB = bin; g_cumB = c; }
        c += h;
    }
}

__global__ void k_hist2() {
    unsigned bA = g_bA, bB = g_bB;
    const uint4* p = (const uint4*)g_Wc;
    int i = blockIdx.x * blockDim.x + threadIdx.x;
    int stride = gridDim.x * blockDim.x;
    for (; i < N_PIX; i += stride) {
        uint4 u = p[i];
        unsigned h0 = u.x >> 16, h1 = u.y >> 16, h2 = u.z >> 16, h3 = u.w >> 16;
        if (h0 == bA) atomicAdd(&g_hist2a[u.x & 0xFFFFu], 1u);
        if (h0 == bB) atomicAdd(&g_hist2b[u.x & 0xFFFFu], 1u);
        if (h1 == bA) atomicAdd(&g_hist2a[u.y & 0xFFFFu], 1u);
        if (h1 == bB) atomicAdd(&g_hist2b[u.y & 0xFFFFu], 1u);
        if (h2 == bA) atomicAdd(&g_hist2a[u.z & 0xFFFFu], 1u);
        if (h2 == bB) atomicAdd(&g_hist2b[u.z & 0xFFFFu], 1u);
        if (h3 == bA) atomicAdd(&g_hist2a[u.w & 0xFFFFu], 1u);
        if (h3 == bB) atomicAdd(&g_hist2b[u.w & 0xFFFFu], 1u);
    }
}

__device__ __forceinline__ void select_low(const unsigned* __restrict__ hist,
                                           unsigned rank, unsigned hi_bits,
                                           unsigned* chunk, float* out_val) {
    int tid = threadIdx.x;
    unsigned s = 0;
    for (int k = 0; k < 64; k++) s += hist[tid * 64 + k];
    chunk[tid] = s;
    __syncthreads();
    if (tid == 0) {
        unsigned run = 0;
        for (int i = 0; i < 1024; i++) { unsigned c = chunk[i]; chunk[i] = run; run += c; }
    }
    __syncthreads();
    unsigned c = chunk[tid];
    for (int k = 0; k < 64; k++) {
        unsigned h = hist[tid * 64 + k];
        if (rank >= c && rank < c + h)
            *out_val = __uint_as_float((hi_bits << 16) | (unsigned)(tid * 64 + k));
        c += h;
    }
    __syncthreads();
}

__global__ void k_sel2(const float* __restrict__ HtRM) {
    __shared__ unsigned chunk[1024];
    __shared__ float vsh[2];
    select_low(g_hist2a, RANK0 - g_cumA, g_bA, chunk, &vsh[0]);
    select_low(g_hist2b, RANK1 - g_cumB, g_bB, chunk, &vsh[1]);
    if (threadIdx.x == 0) {
        double pos = 0.99 * (double)(TOTAL - 1);
        double fr  = pos - floor(pos);
        double q = (double)vsh[0] + fr * ((double)vsh[1] - (double)vsh[0]);
        g_scale = HtRM[0] / (float)q;
    }
}

// ---------------------------------------------------------------------------
__global__ void k_final(const float* __restrict__ Wt, float* __restrict__ out) {
    __shared__ float sw[12];
    if (threadIdx.x < 12) sw[threadIdx.x] = Wt[threadIdx.x];
    __syncthreads();
    float wt[12];
#pragma unroll
    for (int t = 0; t < 12; t++) wt[t] = sw[t];
    float sc = g_scale;
    const int NG = N_PIX / 4;
    float4* out4 = (float4*)out;
    int i = blockIdx.x * blockDim.x + threadIdx.x;
    int stride = gridDim.x * blockDim.x;
    for (int g = i; g < NG; g += stride) {
        float4 cc[4];
#pragma unroll
        for (int q = 0; q < 4; q++) {
            float4 c4 = g_Wc[4 * g + q];
            cc[q] = make_float4(c4.x * sc, c4.y * sc, c4.z * sc, c4.w * sc);
        }
#pragma unroll
        for (int c = 0; c < 3; c++) {
            float4 o;
            float* op = &o.x;
#pragma unroll
            for (int q = 0; q < 4; q++) {
                float t = wt[c*4+0]*cc[q].x + wt[c*4+1]*cc[q].y
                        + wt[c*4+2]*cc[q].z + wt[c*4+3]*cc[q].w;
                float e = __expf(-t);
                op[q] = fminf(fmaxf(e, 0.0f), 1.0f);
            }
            out4[c * NG + g] = o;
        }
    }
}

// ---------------------------------------------------------------------------
extern "C" void kernel_launch(void* const* d_in, const int* in_sizes, int n_in,
                              void* d_out, int out_size) {
    const float* pic = (const float*)d_in[0];
    const float* Wt  = (const float*)d_in[1];
    const float* Ht  = (const float*)d_in[2];
    const float* W0  = (const float*)d_in[3];
    const float* H0  = (const float*)d_in[4];
    float* out = (float*)d_out;

    static int smem_set = 0;
    if (!smem_set) {
        cudaFuncSetAttribute(k_loop, cudaFuncAttributeMaxDynamicSharedMemorySize,
                             SMEM_BYTES);
        smem_set = 1;
    }

    k_init_a<<<592, 256>>>();                   // launch 1
    k_init_b<<<128, 256>>>();                   // launch 2
    k_init_c<<<1, 32>>>();                      // launch 3
    k_loop<<<GRID, NTHR, SMEM_BYTES>>>(pic, W0, H0);   // launch 4 <- ncu capture
    k_sel1<<<1, 1024>>>();
    k_hist2<<<592, 256>>>();
    k_sel2<<<1, 1024>>>(Ht);
    k_final<<<592, 256>>>(Wt, out);
}

// round 10
// speedup vs baseline: 1.5796x; 1.5796x over previous
#include <cuda_runtime.h>
#include <math.h>
#include <stdint.h>

// ---------------------------------------------------------------------------
// HE_ColorNormalization, SMEM-resident persistent NMF, batch-2 ILP sweep.
//   d_in[0] pic float32 (3,1024,1024) | d_in[1] W_target (3,4) | d_in[2] Ht_RM ()
//   d_in[3] W0 (N,4) | d_in[4] H0 (3,4)    Output: float32 (3,1024,1024)
// 148 CTAs x 512 thr, 1 CTA/SM; Wc + V (padded to 7168 px, 196KB) in smem.
// ---------------------------------------------------------------------------

#define N_PIX    1048576
#define N_ITERS  100
#define EPSF     1e-8f
#define GRID     148
#define NTHR     512
#define PPC      7086                    // pixels owned per CTA
#define KMAX     14
#define PPC_PAD  (KMAX * NTHR)           // 7168, zero-padded tail
#define TOTAL    (4 * N_PIX)
#define RANK0    4152359u                // floor(0.99*(TOTAL-1))
#define RANK1    4152360u
#define HREP     16
#define SMEM_BYTES (PPC_PAD * 28)        // 200704 bytes

typedef unsigned long long u64;

__device__ __forceinline__ u64 pk2(float lo, float hi) {
    u64 r; asm("mov.b64 %0, {%1, %2};" : "=l"(r) : "f"(lo), "f"(hi)); return r;
}
__device__ __forceinline__ void upk2(u64 v, float& lo, float& hi) {
    asm("mov.b64 {%0, %1}, %2;" : "=f"(lo), "=f"(hi) : "l"(v));
}
__device__ __forceinline__ u64 fma2_(u64 a, u64 b, u64 c) {
    u64 d; asm("fma.rn.f32x2 %0, %1, %2, %3;" : "=l"(d) : "l"(a), "l"(b), "l"(c)); return d;
}
__device__ __forceinline__ u64 mul2_(u64 a, u64 b) {
    u64 d; asm("mul.rn.f32x2 %0, %1, %2;" : "=l"(d) : "l"(a), "l"(b)); return d;
}

// Scratch (static device globals: no allocation allowed)
__device__ float4   g_Wc[N_PIX];
__device__ float    g_part[2][22][GRID];
__device__ unsigned g_arrive;
__device__ unsigned g_hist1[HREP * 65536];
__device__ unsigned g_hist2a[65536];
__device__ unsigned g_hist2b[65536];
__device__ unsigned g_bA, g_bB, g_cumA, g_cumB;
__device__ float    g_scale;

__device__ __forceinline__ float od_clip(float x) {
    x = fminf(fmaxf(x, 0.01f), 0.99f);
    return -__logf(x);
}

// --------------------------------------------------------------------------
__global__ void k_init_a() {
    int i = blockIdx.x * blockDim.x + threadIdx.x;
    int stride = gridDim.x * blockDim.x;
    uint4 z = make_uint4(0u, 0u, 0u, 0u);
    uint4* h1 = (uint4*)g_hist1;
    for (int h = i; h < HREP * 65536 / 4; h += stride) h1[h] = z;
}
__global__ void k_init_b() {
    int i = blockIdx.x * blockDim.x + threadIdx.x;
    int stride = gridDim.x * blockDim.x;
    uint4 z = make_uint4(0u, 0u, 0u, 0u);
    uint4* h2a = (uint4*)g_hist2a;
    uint4* h2b = (uint4*)g_hist2b;
    for (int h = i; h < 65536 / 4; h += stride) { h2a[h] = z; h2b[h] = z; }
}
__global__ void k_init_c() {
    if (threadIdx.x == 0 && blockIdx.x == 0) g_arrive = 0u;
}

// --------------------------------------------------------------------------
__global__ __launch_bounds__(NTHR, 1) void k_loop(const float* __restrict__ pic,
                                                  const float* __restrict__ W0,
                                                  const float* __restrict__ H0) {
    extern __shared__ float smem_dyn[];
    float4* swc = (float4*)smem_dyn;            // [PPC_PAD]
    float*  sv0 = (float*)(swc + PPC_PAD);      // [PPC_PAD]
    float*  sv1 = sv0 + PPC_PAD;
    float*  sv2 = sv1 + PPC_PAD;

    __shared__ float sHd[12];
    __shared__ float red[NTHR / 32][22];
    __shared__ float tot[22];

    const int tid  = threadIdx.x;
    const int cta  = blockIdx.x;
    const int warp = tid >> 5, lane = tid & 31;
    const int base = cta * PPC;

    if (tid < 12) sHd[tid] = H0[tid];

    // Prologue: load slab (zero the pad so it contributes nothing)
    const float4* w04 = (const float4*)W0;
    for (int l = tid; l < PPC_PAD; l += NTHR) {
        int p = base + l;
        bool ok = (l < PPC) && (p < N_PIX);
        if (ok) {
            swc[l] = w04[p];
            sv0[l] = od_clip(pic[p]);
            sv1[l] = od_clip(pic[N_PIX + p]);
            sv2[l] = od_clip(pic[2 * N_PIX + p]);
        } else {
            swc[l] = make_float4(0.f, 0.f, 0.f, 0.f);
            sv0[l] = 0.f; sv1[l] = 0.f; sv2[l] = 0.f;
        }
    }
    __syncthreads();

    unsigned* hist = &g_hist1[(cta & (HREP - 1)) * 65536];

    for (int iter = 0; iter < N_ITERS; iter++) {
        float hd[12];
#pragma unroll
        for (int t = 0; t < 12; t++) hd[t] = sHd[t];

        float G[16];
#pragma unroll
        for (int k = 0; k < 4; k++)
#pragma unroll
            for (int j = 0; j < 4; j++)
                G[k*4+j] = hd[k]*hd[j] + hd[4+k]*hd[4+j] + hd[8+k]*hd[8+j];

        u64 hd2[3][2], G2[4][2];
#pragma unroll
        for (int c = 0; c < 3; c++) {
            hd2[c][0] = pk2(hd[c*4+0], hd[c*4+1]);
            hd2[c][1] = pk2(hd[c*4+2], hd[c*4+3]);
        }
#pragma unroll
        for (int k = 0; k < 4; k++) {
            G2[k][0] = pk2(G[k*4+0], G[k*4+1]);
            G2[k][1] = pk2(G[k*4+2], G[k*4+3]);
        }
        const u64 eps2 = pk2(EPSF, EPSF);

        u64 aA[3][2];
        float aB[10];
#pragma unroll
        for (int c = 0; c < 3; c++) { aA[c][0] = 0ull; aA[c][1] = 0ull; }
#pragma unroll
        for (int t = 0; t < 10; t++) aB[t] = 0.0f;

        const bool last = (iter == N_ITERS - 1);

        // Batch-of-2 sweep: both loads precede both stores; constant offsets.
#pragma unroll
        for (int kb = 0; kb < KMAX / 2; kb++) {
            const int l0 = tid + (2 * kb) * NTHR;
            const int l1 = l0 + NTHR;

            float4 wA = swc[l0];
            float4 wB = swc[l1];
            float vA0 = sv0[l0], vA1 = sv1[l0], vA2 = sv2[l0];
            float vB0 = sv0[l1], vB1 = sv1[l1], vB2 = sv2[l1];

            // ---- pixel A
            u64 vbA0 = pk2(vA0, vA0), vbA1 = pk2(vA1, vA1), vbA2 = pk2(vA2, vA2);
            u64 nA0 = fma2_(vbA0, hd2[0][0], fma2_(vbA1, hd2[1][0], mul2_(vbA2, hd2[2][0])));
            u64 nA1 = fma2_(vbA0, hd2[0][1], fma2_(vbA1, hd2[1][1], mul2_(vbA2, hd2[2][1])));
            u64 wbA0 = pk2(wA.x, wA.x), wbA1 = pk2(wA.y, wA.y);
            u64 wbA2 = pk2(wA.z, wA.z), wbA3 = pk2(wA.w, wA.w);
            u64 dA0 = fma2_(wbA0, G2[0][0], fma2_(wbA1, G2[1][0],
                      fma2_(wbA2, G2[2][0], fma2_(wbA3, G2[3][0], eps2))));
            u64 dA1 = fma2_(wbA0, G2[0][1], fma2_(wbA1, G2[1][1],
                      fma2_(wbA2, G2[2][1], fma2_(wbA3, G2[3][1], eps2))));

            // ---- pixel B
            u64 vbB0 = pk2(vB0, vB0), vbB1 = pk2(vB1, vB1), vbB2 = pk2(vB2, vB2);
            u64 nB0 = fma2_(vbB0, hd2[0][0], fma2_(vbB1, hd2[1][0], mul2_(vbB2, hd2[2][0])));
            u64 nB1 = fma2_(vbB0, hd2[0][1], fma2_(vbB1, hd2[1][1], mul2_(vbB2, hd2[2][1])));
            u64 wbB0 = pk2(wB.x, wB.x), wbB1 = pk2(wB.y, wB.y);
            u64 wbB2 = pk2(wB.z, wB.z), wbB3 = pk2(wB.w, wB.w);
            u64 dB0 = fma2_(wbB0, G2[0][0], fma2_(wbB1, G2[1][0],
                      fma2_(wbB2, G2[2][0], fma2_(wbB3, G2[3][0], eps2))));
            u64 dB1 = fma2_(wbB0, G2[0][1], fma2_(wbB1, G2[1][1],
                      fma2_(wbB2, G2[2][1], fma2_(wbB3, G2[3][1], eps2))));

            float nuA0, nuA1, nuA2, nuA3, deA0, deA1, deA2, deA3;
            upk2(nA0, nuA0, nuA1); upk2(nA1, nuA2, nuA3);
            upk2(dA0, deA0, deA1); upk2(dA1, deA2, deA3);
            float nuB0, nuB1, nuB2, nuB3, deB0, deB1, deB2, deB3;
            upk2(nB0, nuB0, nuB1); upk2(nB1, nuB2, nuB3);
            upk2(dB0, deB0, deB1); upk2(dB1, deB2, deB3);

            float nA_0 = wA.x * __fdividef(nuA0, deA0);
            float nA_1 = wA.y * __fdividef(nuA1, deA1);
            float nA_2 = wA.z * __fdividef(nuA2, deA2);
            float nA_3 = wA.w * __fdividef(nuA3, deA3);
            float nB_0 = wB.x * __fdividef(nuB0, deB0);
            float nB_1 = wB.y * __fdividef(nuB1, deB1);
            float nB_2 = wB.z * __fdividef(nuB2, deB2);
            float nB_3 = wB.w * __fdividef(nuB3, deB3);

            swc[l0] = make_float4(nA_0, nA_1, nA_2, nA_3);
            swc[l1] = make_float4(nB_0, nB_1, nB_2, nB_3);

            // accumulate A = V*nw (packed), B = Gram (scalar, 10 sym values)
            u64 npA0 = pk2(nA_0, nA_1), npA1 = pk2(nA_2, nA_3);
            u64 npB0 = pk2(nB_0, nB_1), npB1 = pk2(nB_2, nB_3);
            aA[0][0] = fma2_(vbA0, npA0, aA[0][0]); aA[0][1] = fma2_(vbA0, npA1, aA[0][1]);
            aA[1][0] = fma2_(vbA1, npA0, aA[1][0]); aA[1][1] = fma2_(vbA1, npA1, aA[1][1]);
            aA[2][0] = fma2_(vbA2, npA0, aA[2][0]); aA[2][1] = fma2_(vbA2, npA1, aA[2][1]);
            aA[0][0] = fma2_(vbB0, npB0, aA[0][0]); aA[0][1] = fma2_(vbB0, npB1, aA[0][1]);
            aA[1][0] = fma2_(vbB1, npB0, aA[1][0]); aA[1][1] = fma2_(vbB1, npB1, aA[1][1]);
            aA[2][0] = fma2_(vbB2, npB0, aA[2][0]); aA[2][1] = fma2_(vbB2, npB1, aA[2][1]);

            aB[0] += nA_0*nA_0 + nB_0*nB_0;
            aB[1] += nA_0*nA_1 + nB_0*nB_1;
            aB[2] += nA_0*nA_2 + nB_0*nB_2;
            aB[3] += nA_0*nA_3 + nB_0*nB_3;
            aB[4] += nA_1*nA_1 + nB_1*nB_1;
            aB[5] += nA_1*nA_2 + nB_1*nB_2;
            aB[6] += nA_1*nA_3 + nB_1*nB_3;
            aB[7] += nA_2*nA_2 + nB_2*nB_2;
            aB[8] += nA_2*nA_3 + nB_2*nB_3;
            aB[9] += nA_3*nA_3 + nB_3*nB_3;

            if (last) {
                int p0 = base + l0, p1 = base + l1;
                if (l0 < PPC && p0 < N_PIX) {
                    g_Wc[p0] = make_float4(nA_0, nA_1, nA_2, nA_3);
                    atomicAdd(&hist[__float_as_uint(nA_0) >> 16], 1u);
                    atomicAdd(&hist[__float_as_uint(nA_1) >> 16], 1u);
                    atomicAdd(&hist[__float_as_uint(nA_2) >> 16], 1u);
                    atomicAdd(&hist[__float_as_uint(nA_3) >> 16], 1u);
                }
                if (l1 < PPC && p1 < N_PIX) {
                    g_Wc[p1] = make_float4(nB_0, nB_1, nB_2, nB_3);
                    atomicAdd(&hist[__float_as_uint(nB_0) >> 16], 1u);
                    atomicAdd(&hist[__float_as_uint(nB_1) >> 16], 1u);
                    atomicAdd(&hist[__float_as_uint(nB_2) >> 16], 1u);
                    atomicAdd(&hist[__float_as_uint(nB_3) >> 16], 1u);
                }
            }
        }

        if (last) break;

        float acc[22];
        upk2(aA[0][0], acc[0],  acc[1]);  upk2(aA[0][1], acc[2],  acc[3]);
        upk2(aA[1][0], acc[4],  acc[5]);  upk2(aA[1][1], acc[6],  acc[7]);
        upk2(aA[2][0], acc[8],  acc[9]);  upk2(aA[2][1], acc[10], acc[11]);
#pragma unroll
        for (int t = 0; t < 10; t++) acc[12 + t] = aB[t];

#pragma unroll
        for (int t = 0; t < 22; t++)
#pragma unroll
            for (int off = 16; off > 0; off >>= 1)
                acc[t] += __shfl_down_sync(0xFFFFFFFFu, acc[t], off);
        if (lane == 0) {
#pragma unroll
            for (int t = 0; t < 22; t++) red[warp][t] = acc[t];
        }
        __syncthreads();
        if (tid < 22) {
            float s = 0.0f;
#pragma unroll
            for (int w = 0; w < NTHR / 32; w++) s += red[w][tid];
            g_part[iter & 1][tid][cta] = s;
        }
        __syncthreads();

        // grid barrier (R8 form: atomicAdd + volatile spin)
        if (tid == 0) {
            __threadfence();
            atomicAdd(&g_arrive, 1u);
            const unsigned target = (unsigned)(iter + 1) * (unsigned)GRID;
            const volatile unsigned* va = &g_arrive;
            while (*va < target) __nanosleep(32);
            __threadfence();
        }
        __syncthreads();

        // all CTAs reduce partials in fixed order (deterministic)
        for (int v = warp; v < 22; v += NTHR / 32) {
            float s = 0.0f;
            for (int b = lane; b < GRID; b += 32) s += g_part[iter & 1][v][b];
#pragma unroll
            for (int off = 16; off > 0; off >>= 1)
                s += __shfl_down_sync(0xFFFFFFFFu, s, off);
            if (lane == 0) tot[v] = s;
        }
        __syncthreads();

        // parallel Hd update: 12 threads, ALL operands from SHARED memory
        // (dynamic LDS is fine; never index a register array dynamically)
        if (tid < 32) {
            float nv = 0.0f;
            if (tid < 12) {
                int c = tid >> 2, j = tid & 3;
                float den = EPSF;
#pragma unroll
                for (int k = 0; k < 4; k++) {
                    int a = k < j ? k : j;
                    int b = k < j ? j : k;
                    int idx = a * 4 - ((a * (a + 1)) >> 1) + b;
                    den += sHd[c * 4 + k] * tot[12 + idx];
                }
                nv = sHd[tid] * __fdividef(tot[c * 4 + j], den);
            }
            __syncwarp();
            if (tid < 12) sHd[tid] = nv;
        }
        __syncthreads();
    }
}

// ---------------------------------------------------------------------------
__global__ void k_sel1() {
    __shared__ unsigned chunk[1024];
    int tid = threadIdx.x;
    unsigned s = 0;
    for (int k = 0; k < 64; k++) {
        unsigned bin = tid * 64 + k;
        unsigned c = 0;
#pragma unroll
        for (int r = 0; r < HREP; r++) c += g_hist1[r * 65536 + bin];
        s += c;
    }
    chunk[tid] = s;
    __syncthreads();
    if (tid == 0) {
        unsigned run = 0;
        for (int i = 0; i < 1024; i++) { unsigned c = chunk[i]; chunk[i] = run; run += c; }
    }
    __syncthreads();
    unsigned c = chunk[tid];
    for (int k = 0; k < 64; k++) {
        unsigned bin = tid * 64 + k;
        unsigned h = 0;
#pragma unroll
        for (int r = 0; r < HREP; r++) h += g_hist1[r * 65536 + bin];
        if (RANK0 >= c && RANK0 < c + h) { g_bA = bin; g_cumA = c; }
        if (RANK1 >= c && RANK1 < c + h) { g_bB = bin; g_cumB = c; }
        c += h;
    }
}

__global__ void k_hist2() {
    unsigned bA = g_bA, bB = g_bB;
    const uint4* p = (const uint4*)g_Wc;
    int i = blockIdx.x * blockDim.x + threadIdx.x;
    int stride = gridDim.x * blockDim.x;
    for (; i < N_PIX; i += stride) {
        uint4 u = p[i];
        unsigned h0 = u.x >> 16, h1 = u.y >> 16, h2 = u.z >> 16, h3 = u.w >> 16;
        if (h0 == bA) atomicAdd(&g_hist2a[u.x & 0xFFFFu], 1u);
        if (h0 == bB) atomicAdd(&g_hist2b[u.x & 0xFFFFu], 1u);
        if (h1 == bA) atomicAdd(&g_hist2a[u.y & 0xFFFFu], 1u);
        if (h1 == bB) atomicAdd(&g_hist2b[u.y & 0xFFFFu], 1u);
        if (h2 == bA) atomicAdd(&g_hist2a[u.z & 0xFFFFu], 1u);
        if (h2 == bB) atomicAdd(&g_hist2b[u.z & 0xFFFFu], 1u);
        if (h3 == bA) atomicAdd(&g_hist2a[u.w & 0xFFFFu], 1u);
        if (h3 == bB) atomicAdd(&g_hist2b[u.w & 0xFFFFu], 1u);
    }
}

__device__ __forceinline__ void select_low(const unsigned* __restrict__ hist,
                                           unsigned rank, unsigned hi_bits,
                                           unsigned* chunk, float* out_val) {
    int tid = threadIdx.x;
    unsigned s = 0;
    for (int k = 0; k < 64; k++) s += hist[tid * 64 + k];
    chunk[tid] = s;
    __syncthreads();
    if (tid == 0) {
        unsigned run = 0;
        for (int i = 0; i < 1024; i++) { unsigned c = chunk[i]; chunk[i] = run; run += c; }
    }
    __syncthreads();
    unsigned c = chunk[tid];
    for (int k = 0; k < 64; k++) {
        unsigned h = hist[tid * 64 + k];
        if (rank >= c && rank < c + h)
            *out_val = __uint_as_float((hi_bits << 16) | (unsigned)(tid * 64 + k));
        c += h;
    }
    __syncthreads();
}

__global__ void k_sel2(const float* __restrict__ HtRM) {
    __shared__ unsigned chunk[1024];
    __shared__ float vsh[2];
    select_low(g_hist2a, RANK0 - g_cumA, g_bA, chunk, &vsh[0]);
    select_low(g_hist2b, RANK1 - g_cumB, g_bB, chunk, &vsh[1]);
    if (threadIdx.x == 0) {
        double pos = 0.99 * (double)(TOTAL - 1);
        double fr  = pos - floor(pos);
        double q = (double)vsh[0] + fr * ((double)vsh[1] - (double)vsh[0]);
        g_scale = HtRM[0] / (float)q;
    }
}

// ---------------------------------------------------------------------------
__global__ void k_final(const float* __restrict__ Wt, float* __restrict__ out) {
    __shared__ float sw[12];
    if (threadIdx.x < 12) sw[threadIdx.x] = Wt[threadIdx.x];
    __syncthreads();
    float wt[12];
#pragma unroll
    for (int t = 0; t < 12; t++) wt[t] = sw[t];
    float sc = g_scale;
    const int NG = N_PIX / 4;
    float4* out4 = (float4*)out;
    int i = blockIdx.x * blockDim.x + threadIdx.x;
    int stride = gridDim.x * blockDim.x;
    for (int g = i; g < NG; g += stride) {
        float4 cc[4];
#pragma unroll
        for (int q = 0; q < 4; q++) {
            float4 c4 = g_Wc[4 * g + q];
            cc[q] = make_float4(c4.x * sc, c4.y * sc, c4.z * sc, c4.w * sc);
        }
#pragma unroll
        for (int c = 0; c < 3; c++) {
            float4 o;
            float* op = &o.x;
#pragma unroll
            for (int q = 0; q < 4; q++) {
                float t = wt[c*4+0]*cc[q].x + wt[c*4+1]*cc[q].y
                        + wt[c*4+2]*cc[q].z + wt[c*4+3]*cc[q].w;
                float e = __expf(-t);
                op[q] = fminf(fmaxf(e, 0.0f), 1.0f);
            }
            out4[c * NG + g] = o;
        }
    }
}

// ---------------------------------------------------------------------------
extern "C" void kernel_launch(void* const* d_in, const int* in_sizes, int n_in,
                              void* d_out, int out_size) {
    const float* pic = (const float*)d_in[0];
    const float* Wt  = (const float*)d_in[1];
    const float* Ht  = (const float*)d_in[2];
    const float* W0  = (const float*)d_in[3];
    const float* H0  = (const float*)d_in[4];
    float* out = (float*)d_out;

    static int smem_set = 0;
    if (!smem_set) {
        cudaFuncSetAttribute(k_loop, cudaFuncAttributeMaxDynamicSharedMemorySize,
                             SMEM_BYTES);
        smem_set = 1;
    }

    k_init_a<<<592, 256>>>();                          // launch 1
    k_init_b<<<128, 256>>>();                          // launch 2
    k_init_c<<<1, 32>>>();                             // launch 3
    k_loop<<<GRID, NTHR, SMEM_BYTES>>>(pic, W0, H0);   // launch 4
    k_sel1<<<1, 1024>>>();
    k_hist2<<<592, 256>>>();
    k_sel2<<<1, 1024>>>(Ht);
    k_final<<<592, 256>>>(Wt, out);
}

// round 12
// speedup vs baseline: 1.6118x; 1.0204x over previous
#include <cuda_runtime.h>
#include <math.h>
#include <stdint.h>

// ---------------------------------------------------------------------------
// HE_ColorNormalization, SMEM-resident persistent NMF, scalar 24-warp sweep.
//   d_in[0] pic float32 (3,1024,1024) | d_in[1] W_target (3,4) | d_in[2] Ht_RM ()
//   d_in[3] W0 (N,4) | d_in[4] H0 (3,4)    Output: float32 (3,1024,1024)
// 148 CTAs x 768 thr (24 warps/SM, 85-reg budget); Wc + V in smem (215KB).
// Fully scalar math: no f32x2 pack/unpack MOV overhead.
// ---------------------------------------------------------------------------

#define N_PIX    1048576
#define N_ITERS  100
#define EPSF     1e-8f
#define GRID     148
#define NTHR     768
#define PPC      7086                    // pixels owned per CTA
#define KMAX     10
#define PPC_PAD  (KMAX * NTHR)           // 7680, zero-padded tail
#define TOTAL    (4 * N_PIX)
#define RANK0    4152359u                // floor(0.99*(TOTAL-1))
#define RANK1    4152360u
#define HREP     16
#define SMEM_BYTES (PPC_PAD * 28)        // 215040 bytes

// Scratch (static device globals: no allocation allowed)
__device__ float4   g_Wc[N_PIX];
__device__ float    g_part[2][22][GRID];
__device__ unsigned g_arrive;
__device__ unsigned g_hist1[HREP * 65536];
__device__ unsigned g_hist2a[65536];
__device__ unsigned g_hist2b[65536];
__device__ unsigned g_bA, g_bB, g_cumA, g_cumB;
__device__ float    g_scale;

__device__ __forceinline__ float od_clip(float x) {
    x = fminf(fmaxf(x, 0.01f), 0.99f);
    return -__logf(x);
}

// --------------------------------------------------------------------------
__global__ void k_init_a() {
    int i = blockIdx.x * blockDim.x + threadIdx.x;
    int stride = gridDim.x * blockDim.x;
    uint4 z = make_uint4(0u, 0u, 0u, 0u);
    uint4* h1 = (uint4*)g_hist1;
    for (int h = i; h < HREP * 65536 / 4; h += stride) h1[h] = z;
}
__global__ void k_init_b() {
    int i = blockIdx.x * blockDim.x + threadIdx.x;
    int stride = gridDim.x * blockDim.x;
    uint4 z = make_uint4(0u, 0u, 0u, 0u);
    uint4* h2a = (uint4*)g_hist2a;
    uint4* h2b = (uint4*)g_hist2b;
    for (int h = i; h < 65536 / 4; h += stride) { h2a[h] = z; h2b[h] = z; }
}
__global__ void k_init_c() {
    if (threadIdx.x == 0 && blockIdx.x == 0) g_arrive = 0u;
}

// --------------------------------------------------------------------------
__global__ __launch_bounds__(NTHR, 1) void k_loop(const float* __restrict__ pic,
                                                  const float* __restrict__ W0,
                                                  const float* __restrict__ H0) {
    extern __shared__ float smem_dyn[];
    float4* swc = (float4*)smem_dyn;            // [PPC_PAD]
    float*  sv0 = (float*)(swc + PPC_PAD);      // [PPC_PAD]
    float*  sv1 = sv0 + PPC_PAD;
    float*  sv2 = sv1 + PPC_PAD;

    __shared__ float sHd[12];
    __shared__ float red[NTHR / 32][22];
    __shared__ float tot[22];

    const int tid  = threadIdx.x;
    const int cta  = blockIdx.x;
    const int warp = tid >> 5, lane = tid & 31;
    const int base = cta * PPC;

    if (tid < 12) sHd[tid] = H0[tid];

    // Prologue: load slab (zero the pad so it contributes nothing)
    const float4* w04 = (const float4*)W0;
    for (int l = tid; l < PPC_PAD; l += NTHR) {
        int p = base + l;
        bool ok = (l < PPC) && (p < N_PIX);
        if (ok) {
            swc[l] = w04[p];
            sv0[l] = od_clip(pic[p]);
            sv1[l] = od_clip(pic[N_PIX + p]);
            sv2[l] = od_clip(pic[2 * N_PIX + p]);
        } else {
            swc[l] = make_float4(0.f, 0.f, 0.f, 0.f);
            sv0[l] = 0.f; sv1[l] = 0.f; sv2[l] = 0.f;
        }
    }
    __syncthreads();

    unsigned* hist = &g_hist1[(cta & (HREP - 1)) * 65536];

    for (int iter = 0; iter < N_ITERS; iter++) {
        float hd[12];
#pragma unroll
        for (int t = 0; t < 12; t++) hd[t] = sHd[t];

        // Gram G[k][j] = sum_c hd[c][k]*hd[c][j]
        float G[16];
#pragma unroll
        for (int k = 0; k < 4; k++)
#pragma unroll
            for (int j = 0; j < 4; j++)
                G[k*4+j] = hd[k]*hd[j] + hd[4+k]*hd[4+j] + hd[8+k]*hd[8+j];

        float acc[22];
#pragma unroll
        for (int t = 0; t < 22; t++) acc[t] = 0.0f;

        const bool last = (iter == N_ITERS - 1);

#pragma unroll
        for (int k = 0; k < KMAX; k++) {
            const int l = tid + k * NTHR;

            float4 w = swc[l];
            float v0 = sv0[l], v1 = sv1[l], v2 = sv2[l];

            float num0 = v0*hd[0] + v1*hd[4] + v2*hd[8];
            float num1 = v0*hd[1] + v1*hd[5] + v2*hd[9];
            float num2 = v0*hd[2] + v1*hd[6] + v2*hd[10];
            float num3 = v0*hd[3] + v1*hd[7] + v2*hd[11];

            float den0 = w.x*G[0]  + w.y*G[4]  + w.z*G[8]  + w.w*G[12] + EPSF;
            float den1 = w.x*G[1]  + w.y*G[5]  + w.z*G[9]  + w.w*G[13] + EPSF;
            float den2 = w.x*G[2]  + w.y*G[6]  + w.z*G[10] + w.w*G[14] + EPSF;
            float den3 = w.x*G[3]  + w.y*G[7]  + w.z*G[11] + w.w*G[15] + EPSF;

            float nw0 = w.x * __fdividef(num0, den0);
            float nw1 = w.y * __fdividef(num1, den1);
            float nw2 = w.z * __fdividef(num2, den2);
            float nw3 = w.w * __fdividef(num3, den3);
            swc[l] = make_float4(nw0, nw1, nw2, nw3);

            // A = V @ nw  (12)
            acc[0]  += v0*nw0;  acc[1]  += v0*nw1;  acc[2]  += v0*nw2;  acc[3]  += v0*nw3;
            acc[4]  += v1*nw0;  acc[5]  += v1*nw1;  acc[6]  += v1*nw2;  acc[7]  += v1*nw3;
            acc[8]  += v2*nw0;  acc[9]  += v2*nw1;  acc[10] += v2*nw2;  acc[11] += v2*nw3;
            // B = nw (x) nw, symmetric 10
            acc[12] += nw0*nw0; acc[13] += nw0*nw1; acc[14] += nw0*nw2; acc[15] += nw0*nw3;
            acc[16] += nw1*nw1; acc[17] += nw1*nw2; acc[18] += nw1*nw3;
            acc[19] += nw2*nw2; acc[20] += nw2*nw3; acc[21] += nw3*nw3;

            if (last) {
                int p = base + l;
                if (l < PPC && p < N_PIX) {
                    g_Wc[p] = make_float4(nw0, nw1, nw2, nw3);
                    atomicAdd(&hist[__float_as_uint(nw0) >> 16], 1u);
                    atomicAdd(&hist[__float_as_uint(nw1) >> 16], 1u);
                    atomicAdd(&hist[__float_as_uint(nw2) >> 16], 1u);
                    atomicAdd(&hist[__float_as_uint(nw3) >> 16], 1u);
                }
            }
        }

        if (last) break;

        // CTA reduction
#pragma unroll
        for (int t = 0; t < 22; t++)
#pragma unroll
            for (int off = 16; off > 0; off >>= 1)
                acc[t] += __shfl_down_sync(0xFFFFFFFFu, acc[t], off);
        if (lane == 0) {
#pragma unroll
            for (int t = 0; t < 22; t++) red[warp][t] = acc[t];
        }
        __syncthreads();
        if (tid < 22) {
            float s = 0.0f;
#pragma unroll
            for (int w = 0; w < NTHR / 32; w++) s += red[w][tid];
            g_part[iter & 1][tid][cta] = s;
        }
        __syncthreads();

        // grid barrier (atomicAdd + volatile spin; reset each replay by k_init_c)
        if (tid == 0) {
            __threadfence();
            atomicAdd(&g_arrive, 1u);
            const unsigned target = (unsigned)(iter + 1) * (unsigned)GRID;
            const volatile unsigned* va = &g_arrive;
            while (*va < target) __nanosleep(32);
            __threadfence();
        }
        __syncthreads();

        // all CTAs reduce partials in fixed order (deterministic)
        for (int v = warp; v < 22; v += NTHR / 32) {
            float s = 0.0f;
            for (int b = lane; b < GRID; b += 32) s += g_part[iter & 1][v][b];
#pragma unroll
            for (int off = 16; off > 0; off >>= 1)
                s += __shfl_down_sync(0xFFFFFFFFu, s, off);
            if (lane == 0) tot[v] = s;
        }
        __syncthreads();

        // parallel Hd update: 12 threads, all operands via SHARED memory
        if (tid < 32) {
            float nv = 0.0f;
            if (tid < 12) {
                int c = tid >> 2, j = tid & 3;
                float den = EPSF;
#pragma unroll
                for (int k = 0; k < 4; k++) {
                    int a = k < j ? k : j;
                    int b = k < j ? j : k;
                    int idx = a * 4 - ((a * (a + 1)) >> 1) + b;   // sym(4) packed
                    den += sHd[c * 4 + k] * tot[12 + idx];
                }
                nv = sHd[tid] * __fdividef(tot[c * 4 + j], den);
            }
            __syncwarp();
            if (tid < 12) sHd[tid] = nv;
        }
        __syncthreads();
    }
}

// ---------------------------------------------------------------------------
__global__ void k_sel1() {
    __shared__ unsigned chunk[1024];
    int tid = threadIdx.x;
    unsigned s = 0;
    for (int k = 0; k < 64; k++) {
        unsigned bin = tid * 64 + k;
        unsigned c = 0;
#pragma unroll
        for (int r = 0; r < HREP; r++) c += g_hist1[r * 65536 + bin];
        s += c;
    }
    chunk[tid] = s;
    __syncthreads();
    if (tid == 0) {
        unsigned run = 0;
        for (int i = 0; i < 1024; i++) { unsigned c = chunk[i]; chunk[i] = run; run += c; }
    }
    __syncthreads();
    unsigned c = chunk[tid];
    for (int k = 0; k < 64; k++) {
        unsigned bin = tid * 64 + k;
        unsigned h = 0;
#pragma unroll
        for (int r = 0; r < HREP; r++) h += g_hist1[r * 65536 + bin];
        if (RANK0 >= c && RANK0 < c + h) { g_bA = bin; g_cumA = c; }
        if (RANK1 >= c && RANK1 < c + h) { g_bB = bin; g_cumB = c; }
        c += h;
    }
}

__global__ void k_hist2() {
    unsigned bA = g_bA, bB = g_bB;
    const uint4* p = (const uint4*)g_Wc;
    int i = blockIdx.x * blockDim.x + threadIdx.x;
    int stride = gridDim.x * blockDim.x;
    for (; i < N_PIX; i += stride) {
        uint4 u = p[i];
        unsigned h0 = u.x >> 16, h1 = u.y >> 16, h2 = u.z >> 16, h3 = u.w >> 16;
        if (h0 == bA) atomicAdd(&g_hist2a[u.x & 0xFFFFu], 1u);
        if (h0 == bB) atomicAdd(&g_hist2b[u.x & 0xFFFFu], 1u);
        if (h1 == bA) atomicAdd(&g_hist2a[u.y & 0xFFFFu], 1u);
        if (h1 == bB) atomicAdd(&g_hist2b[u.y & 0xFFFFu], 1u);
        if (h2 == bA) atomicAdd(&g_hist2a[u.z & 0xFFFFu], 1u);
        if (h2 == bB) atomicAdd(&g_hist2b[u.z & 0xFFFFu], 1u);
        if (h3 == bA) atomicAdd(&g_hist2a[u.w & 0xFFFFu], 1u);
        if (h3 == bB) atomicAdd(&g_hist2b[u.w & 0xFFFFu], 1u);
    }
}

__device__ __forceinline__ void select_low(const unsigned* __restrict__ hist,
                                           unsigned rank, unsigned hi_bits,
                                           unsigned* chunk, float* out_val) {
    int tid = threadIdx.x;
    unsigned s = 0;
    for (int k = 0; k < 64; k++) s += hist[tid * 64 + k];
    chunk[tid] = s;
    __syncthreads();
    if (tid == 0) {
        unsigned run = 0;
        for (int i = 0; i < 1024; i++) { unsigned c = chunk[i]; chunk[i] = run; run += c; }
    }
    __syncthreads();
    unsigned c = chunk[tid];
    for (int k = 0; k < 64; k++) {
        unsigned h = hist[tid * 64 + k];
        if (rank >= c && rank < c + h)
            *out_val = __uint_as_float((hi_bits << 16) | (unsigned)(tid * 64 + k));
        c += h;
    }
    __syncthreads();
}

__global__ void k_sel2(const float* __restrict__ HtRM) {
    __shared__ unsigned chunk[1024];
    __shared__ float vsh[2];
    select_low(g_hist2a, RANK0 - g_cumA, g_bA, chunk, &vsh[0]);
    select_low(g_hist2b, RANK1 - g_cumB, g_bB, chunk, &vsh[1]);
    if (threadIdx.x == 0) {
        double pos = 0.99 * (double)(TOTAL - 1);
        double fr  = pos - floor(pos);
        double q = (double)vsh[0] + fr * ((double)vsh[1] - (double)vsh[0]);
        g_scale = HtRM[0] / (float)q;
    }
}

// ---------------------------------------------------------------------------
__global__ void k_final(const float* __restrict__ Wt, float* __restrict__ out) {
    __shared__ float sw[12];
    if (threadIdx.x < 12) sw[threadIdx.x] = Wt[threadIdx.x];
    __syncthreads();
    float wt[12];
#pragma unroll
    for (int t = 0; t < 12; t++) wt[t] = sw[t];
    float sc = g_scale;
    const int NG = N_PIX / 4;
    float4* out4 = (float4*)out;
    int i = blockIdx.x * blockDim.x + threadIdx.x;
    int stride = gridDim.x * blockDim.x;
    for (int g = i; g < NG; g += stride) {
        float4 cc[4];
#pragma unroll
        for (int q = 0; q < 4; q++) {
            float4 c4 = g_Wc[4 * g + q];
            cc[q] = make_float4(c4.x * sc, c4.y * sc, c4.z * sc, c4.w * sc);
        }
#pragma unroll
        for (int c = 0; c < 3; c++) {
            float4 o;
            float* op = &o.x;
#pragma unroll
            for (int q = 0; q < 4; q++) {
                float t = wt[c*4+0]*cc[q].x + wt[c*4+1]*cc[q].y
                        + wt[c*4+2]*cc[q].z + wt[c*4+3]*cc[q].w;
                float e = __expf(-t);
                op[q] = fminf(fmaxf(e, 0.0f), 1.0f);
            }
            out4[c * NG + g] = o;
        }
    }
}

// ---------------------------------------------------------------------------
extern "C" void kernel_launch(void* const* d_in, const int* in_sizes, int n_in,
                              void* d_out, int out_size) {
    const float* pic = (const float*)d_in[0];
    const float* Wt  = (const float*)d_in[1];
    const float* Ht  = (const float*)d_in[2];
    const float* W0  = (const float*)d_in[3];
    const float* H0  = (const float*)d_in[4];
    float* out = (float*)d_out;

    static int smem_set = 0;
    if (!smem_set) {
        cudaFuncSetAttribute(k_loop, cudaFuncAttributeMaxDynamicSharedMemorySize,
                             SMEM_BYTES);
        smem_set = 1;
    }

    k_init_a<<<592, 256>>>();                          // launch 1
    k_init_b<<<128, 256>>>();                          // launch 2
    k_init_c<<<1, 32>>>();                             // launch 3
    k_loop<<<GRID, NTHR, SMEM_BYTES>>>(pic, W0, H0);   // launch 4
    k_sel1<<<1, 1024>>>();
    k_hist2<<<592, 256>>>();
    k_sel2<<<1, 1024>>>(Ht);
    k_final<<<592, 256>>>(Wt, out);
}

// round 13
// speedup vs baseline: 2.9530x; 1.8322x over previous
#include <cuda_runtime.h>
#include <math.h>
#include <stdint.h>

// ---------------------------------------------------------------------------
// HE_ColorNormalization, SMEM-resident persistent NMF, scalar 32-warp sweep.
//   d_in[0] pic float32 (3,1024,1024) | d_in[1] W_target (3,4) | d_in[2] Ht_RM ()
//   d_in[3] W0 (N,4) | d_in[4] H0 (3,4)    Output: float32 (3,1024,1024)
// 148 CTAs x 1024 thr (32 warps/SM, 64-reg budget); Wc + V in smem (200.7KB).
// G kept as 10 unique symmetric values to fit the 64-reg cap without spills.
// ---------------------------------------------------------------------------

#define N_PIX    1048576
#define N_ITERS  100
#define EPSF     1e-8f
#define GRID     148
#define NTHR     1024
#define PPC      7086                    // pixels owned per CTA
#define KMAX     7
#define PPC_PAD  (KMAX * NTHR)           // 7168, zero-padded tail
#define TOTAL    (4 * N_PIX)
#define RANK0    4152359u                // floor(0.99*(TOTAL-1))
#define RANK1    4152360u
#define HREP     16
#define SMEM_BYTES (PPC_PAD * 28)        // 200704 bytes

// Scratch (static device globals: no allocation allowed)
__device__ float4   g_Wc[N_PIX];
__device__ float    g_part[2][22][GRID];
__device__ unsigned g_arrive;
__device__ unsigned g_hist1[HREP * 65536];
__device__ unsigned g_hsum[65536];
__device__ unsigned g_hist2a[65536];
__device__ unsigned g_hist2b[65536];
__device__ unsigned g_bA, g_bB, g_cumA, g_cumB;
__device__ float    g_scale;

__device__ __forceinline__ float od_clip(float x) {
    x = fminf(fmaxf(x, 0.01f), 0.99f);
    return -__logf(x);
}

// --------------------------------------------------------------------------
__global__ void k_init_a() {
    int i = blockIdx.x * blockDim.x + threadIdx.x;
    int stride = gridDim.x * blockDim.x;
    uint4 z = make_uint4(0u, 0u, 0u, 0u);
    uint4* h1 = (uint4*)g_hist1;
    for (int h = i; h < HREP * 65536 / 4; h += stride) h1[h] = z;
}
__global__ void k_init_b() {
    int i = blockIdx.x * blockDim.x + threadIdx.x;
    int stride = gridDim.x * blockDim.x;
    uint4 z = make_uint4(0u, 0u, 0u, 0u);
    uint4* h2a = (uint4*)g_hist2a;
    uint4* h2b = (uint4*)g_hist2b;
    for (int h = i; h < 65536 / 4; h += stride) { h2a[h] = z; h2b[h] = z; }
}
__global__ void k_init_c() {
    if (threadIdx.x == 0 && blockIdx.x == 0) g_arrive = 0u;
}

// --------------------------------------------------------------------------
__global__ __launch_bounds__(NTHR, 1) void k_loop(const float* __restrict__ pic,
                                                  const float* __restrict__ W0,
                                                  const float* __restrict__ H0) {
    extern __shared__ float smem_dyn[];
    float4* swc = (float4*)smem_dyn;            // [PPC_PAD]
    float*  sv0 = (float*)(swc + PPC_PAD);      // [PPC_PAD]
    float*  sv1 = sv0 + PPC_PAD;
    float*  sv2 = sv1 + PPC_PAD;

    __shared__ float sHd[12];
    __shared__ float red[NTHR / 32][22];
    __shared__ float tot[22];

    const int tid  = threadIdx.x;
    const int cta  = blockIdx.x;
    const int warp = tid >> 5, lane = tid & 31;
    const int base = cta * PPC;

    if (tid < 12) sHd[tid] = H0[tid];

    // Prologue: load slab (zero the pad so it contributes nothing)
    const float4* w04 = (const float4*)W0;
    for (int l = tid; l < PPC_PAD; l += NTHR) {
        int p = base + l;
        bool ok = (l < PPC) && (p < N_PIX);
        if (ok) {
            swc[l] = w04[p];
            sv0[l] = od_clip(pic[p]);
            sv1[l] = od_clip(pic[N_PIX + p]);
            sv2[l] = od_clip(pic[2 * N_PIX + p]);
        } else {
            swc[l] = make_float4(0.f, 0.f, 0.f, 0.f);
            sv0[l] = 0.f; sv1[l] = 0.f; sv2[l] = 0.f;
        }
    }
    __syncthreads();

    unsigned* hist = &g_hist1[(cta & (HREP - 1)) * 65536];

    for (int iter = 0; iter < N_ITERS; iter++) {
        float hd[12];
#pragma unroll
        for (int t = 0; t < 12; t++) hd[t] = sHd[t];

        // Gram, 10 unique symmetric values (saves 6 registers vs full 4x4)
        float g00 = hd[0]*hd[0] + hd[4]*hd[4] + hd[8]*hd[8];
        float g01 = hd[0]*hd[1] + hd[4]*hd[5] + hd[8]*hd[9];
        float g02 = hd[0]*hd[2] + hd[4]*hd[6] + hd[8]*hd[10];
        float g03 = hd[0]*hd[3] + hd[4]*hd[7] + hd[8]*hd[11];
        float g11 = hd[1]*hd[1] + hd[5]*hd[5] + hd[9]*hd[9];
        float g12 = hd[1]*hd[2] + hd[5]*hd[6] + hd[9]*hd[10];
        float g13 = hd[1]*hd[3] + hd[5]*hd[7] + hd[9]*hd[11];
        float g22 = hd[2]*hd[2] + hd[6]*hd[6] + hd[10]*hd[10];
        float g23 = hd[2]*hd[3] + hd[6]*hd[7] + hd[10]*hd[11];
        float g33 = hd[3]*hd[3] + hd[7]*hd[7] + hd[11]*hd[11];

        float acc[22];
#pragma unroll
        for (int t = 0; t < 22; t++) acc[t] = 0.0f;

        const bool last = (iter == N_ITERS - 1);

#pragma unroll
        for (int k = 0; k < KMAX; k++) {
            const int l = tid + k * NTHR;

            float4 w = swc[l];
            float v0 = sv0[l], v1 = sv1[l], v2 = sv2[l];

            float den0 = w.x*g00 + w.y*g01 + w.z*g02 + w.w*g03 + EPSF;
            float den1 = w.x*g01 + w.y*g11 + w.z*g12 + w.w*g13 + EPSF;
            float den2 = w.x*g02 + w.y*g12 + w.z*g22 + w.w*g23 + EPSF;
            float den3 = w.x*g03 + w.y*g13 + w.z*g23 + w.w*g33 + EPSF;

            float num0 = v0*hd[0] + v1*hd[4] + v2*hd[8];
            float num1 = v0*hd[1] + v1*hd[5] + v2*hd[9];
            float num2 = v0*hd[2] + v1*hd[6] + v2*hd[10];
            float num3 = v0*hd[3] + v1*hd[7] + v2*hd[11];

            float nw0 = w.x * __fdividef(num0, den0);
            float nw1 = w.y * __fdividef(num1, den1);
            float nw2 = w.z * __fdividef(num2, den2);
            float nw3 = w.w * __fdividef(num3, den3);
            swc[l] = make_float4(nw0, nw1, nw2, nw3);

            // A = V @ nw  (12)
            acc[0]  += v0*nw0;  acc[1]  += v0*nw1;  acc[2]  += v0*nw2;  acc[3]  += v0*nw3;
            acc[4]  += v1*nw0;  acc[5]  += v1*nw1;  acc[6]  += v1*nw2;  acc[7]  += v1*nw3;
            acc[8]  += v2*nw0;  acc[9]  += v2*nw1;  acc[10] += v2*nw2;  acc[11] += v2*nw3;
            // B = nw (x) nw, symmetric 10
            acc[12] += nw0*nw0; acc[13] += nw0*nw1; acc[14] += nw0*nw2; acc[15] += nw0*nw3;
            acc[16] += nw1*nw1; acc[17] += nw1*nw2; acc[18] += nw1*nw3;
            acc[19] += nw2*nw2; acc[20] += nw2*nw3; acc[21] += nw3*nw3;

            if (last) {
                int p = base + l;
                if (l < PPC && p < N_PIX) {
                    g_Wc[p] = make_float4(nw0, nw1, nw2, nw3);
                    atomicAdd(&hist[__float_as_uint(nw0) >> 16], 1u);
                    atomicAdd(&hist[__float_as_uint(nw1) >> 16], 1u);
                    atomicAdd(&hist[__float_as_uint(nw2) >> 16], 1u);
                    atomicAdd(&hist[__float_as_uint(nw3) >> 16], 1u);
                }
            }
        }

        if (last) break;

        // CTA reduction
#pragma unroll
        for (int t = 0; t < 22; t++)
#pragma unroll
            for (int off = 16; off > 0; off >>= 1)
                acc[t] += __shfl_down_sync(0xFFFFFFFFu, acc[t], off);
        if (lane == 0) {
#pragma unroll
            for (int t = 0; t < 22; t++) red[warp][t] = acc[t];
        }
        __syncthreads();
        if (tid < 22) {
            float s = 0.0f;
#pragma unroll
            for (int w = 0; w < NTHR / 32; w++) s += red[w][tid];
            g_part[iter & 1][tid][cta] = s;
        }
        __syncthreads();

        // grid barrier (atomicAdd + volatile spin; reset each replay by k_init_c)
        if (tid == 0) {
            __threadfence();
            atomicAdd(&g_arrive, 1u);
            const unsigned target = (unsigned)(iter + 1) * (unsigned)GRID;
            const volatile unsigned* va = &g_arrive;
            while (*va < target) __nanosleep(32);
            __threadfence();
        }
        __syncthreads();

        // all CTAs reduce partials in fixed order (deterministic)
        for (int v = warp; v < 22; v += NTHR / 32) {
            float s = 0.0f;
            for (int b = lane; b < GRID; b += 32) s += g_part[iter & 1][v][b];
#pragma unroll
            for (int off = 16; off > 0; off >>= 1)
                s += __shfl_down_sync(0xFFFFFFFFu, s, off);
            if (lane == 0) tot[v] = s;
        }
        __syncthreads();

        // parallel Hd update: 12 threads, all operands via SHARED memory
        if (tid < 32) {
            float nv = 0.0f;
            if (tid < 12) {
                int c = tid >> 2, j = tid & 3;
                float den = EPSF;
#pragma unroll
                for (int k = 0; k < 4; k++) {
                    int a = k < j ? k : j;
                    int b = k < j ? j : k;
                    int idx = a * 4 - ((a * (a + 1)) >> 1) + b;   // sym(4) packed
                    den += sHd[c * 4 + k] * tot[12 + idx];
                }
                nv = sHd[tid] * __fdividef(tot[c * 4 + j], den);
            }
            __syncwarp();
            if (tid < 12) sHd[tid] = nv;
        }
        __syncthreads();
    }
}

// ---------------------------------------------------------------------------
// Pre-sum the HREP histogram replicas (full grid) so k_sel1 reads 256KB once.
__global__ void k_hsum() {
    int bin = blockIdx.x * blockDim.x + threadIdx.x;
    if (bin < 65536) {
        unsigned s = 0;
#pragma unroll
        for (int r = 0; r < HREP; r++) s += g_hist1[r * 65536 + bin];
        g_hsum[bin] = s;
    }
}

__global__ void k_sel1() {
    __shared__ unsigned chunk[1024];
    int tid = threadIdx.x;
    unsigned s = 0;
    for (int k = 0; k < 64; k++) s += g_hsum[tid * 64 + k];
    chunk[tid] = s;
    __syncthreads();
    if (tid == 0) {
        unsigned run = 0;
        for (int i = 0; i < 1024; i++) { unsigned c = chunk[i]; chunk[i] = run; run += c; }
    }
    __syncthreads();
    unsigned c = chunk[tid];
    for (int k = 0; k < 64; k++) {
        unsigned bin = tid * 64 + k;
        unsigned h = g_hsum[bin];
        if (RANK0 >= c && RANK0 < c + h) { g_bA = bin; g_cumA = c; }
        if (RANK1 >= c && RANK1 < c + h) { g_bB = bin; g_cumB = c; }
        c += h;
    }
}

__global__ void k_hist2() {
    unsigned bA = g_bA, bB = g_bB;
    const uint4* p = (const uint4*)g_Wc;
    int i = blockIdx.x * blockDim.x + threadIdx.x;
    int stride = gridDim.x * blockDim.x;
    for (; i < N_PIX; i += stride) {
        uint4 u = p[i];
        unsigned h0 = u.x >> 16, h1 = u.y >> 16, h2 = u.z >> 16, h3 = u.w >> 16;
        if (h0 == bA) atomicAdd(&g_hist2a[u.x & 0xFFFFu], 1u);
        if (h0 == bB) atomicAdd(&g_hist2b[u.x & 0xFFFFu], 1u);
        if (h1 == bA) atomicAdd(&g_hist2a[u.y & 0xFFFFu], 1u);
        if (h1 == bB) atomicAdd(&g_hist2b[u.y & 0xFFFFu], 1u);
        if (h2 == bA) atomicAdd(&g_hist2a[u.z & 0xFFFFu], 1u);
        if (h2 == bB) atomicAdd(&g_hist2b[u.z & 0xFFFFu], 1u);
        if (h3 == bA) atomicAdd(&g_hist2a[u.w & 0xFFFFu], 1u);
        if (h3 == bB) atomicAdd(&g_hist2b[u.w & 0xFFFFu], 1u);
    }
}

__device__ __forceinline__ void select_low(const unsigned* __restrict__ hist,
                                           unsigned rank, unsigned hi_bits,
                                           unsigned* chunk, float* out_val) {
    int tid = threadIdx.x;
    unsigned s = 0;
    for (int k = 0; k < 64; k++) s += hist[tid * 64 + k];
    chunk[tid] = s;
    __syncthreads();
    if (tid == 0) {
        unsigned run = 0;
        for (int i = 0; i < 1024; i++) { unsigned c = chunk[i]; chunk[i] = run; run += c; }
    }
    __syncthreads();
    unsigned c = chunk[tid];
    for (int k = 0; k < 64; k++) {
        unsigned h = hist[tid * 64 + k];
        if (rank >= c && rank < c + h)
            *out_val = __uint_as_float((hi_bits << 16) | (unsigned)(tid * 64 + k));
        c += h;
    }
    __syncthreads();
}

__global__ void k_sel2(const float* __restrict__ HtRM) {
    __shared__ unsigned chunk[1024];
    __shared__ float vsh[2];
    select_low(g_hist2a, RANK0 - g_cumA, g_bA, chunk, &vsh[0]);
    select_low(g_hist2b, RANK1 - g_cumB, g_bB, chunk, &vsh[1]);
    if (threadIdx.x == 0) {
        double pos = 0.99 * (double)(TOTAL - 1);
        double fr  = pos - floor(pos);
        double q = (double)vsh[0] + fr * ((double)vsh[1] - (double)vsh[0]);
        g_scale = HtRM[0] / (float)q;
    }
}

// ---------------------------------------------------------------------------
__global__ void k_final(const float* __restrict__ Wt, float* __restrict__ out) {
    __shared__ float sw[12];
    if (threadIdx.x < 12) sw[threadIdx.x] = Wt[threadIdx.x];
    __syncthreads();
    float wt[12];
#pragma unroll
    for (int t = 0; t < 12; t++) wt[t] = sw[t];
    float sc = g_scale;
    const int NG = N_PIX / 4;
    float4* out4 = (float4*)out;
    int i = blockIdx.x * blockDim.x + threadIdx.x;
    int stride = gridDim.x * blockDim.x;
    for (int g = i; g < NG; g += stride) {
        float4 cc[4];
#pragma unroll
        for (int q = 0; q < 4; q++) {
            float4 c4 = g_Wc[4 * g + q];
            cc[q] = make_float4(c4.x * sc, c4.y * sc, c4.z * sc, c4.w * sc);
        }
#pragma unroll
        for (int c = 0; c < 3; c++) {
            float4 o;
            float* op = &o.x;
#pragma unroll
            for (int q = 0; q < 4; q++) {
                float t = wt[c*4+0]*cc[q].x + wt[c*4+1]*cc[q].y
                        + wt[c*4+2]*cc[q].z + wt[c*4+3]*cc[q].w;
                float e = __expf(-t);
                op[q] = fminf(fmaxf(e, 0.0f), 1.0f);
            }
            out4[c * NG + g] = o;
        }
    }
}

// ---------------------------------------------------------------------------
extern "C" void kernel_launch(void* const* d_in, const int* in_sizes, int n_in,
                              void* d_out, int out_size) {
    const float* pic = (const float*)d_in[0];
    const float* Wt  = (const float*)d_in[1];
    const float* Ht  = (const float*)d_in[2];
    const float* W0  = (const float*)d_in[3];
    const float* H0  = (const float*)d_in[4];
    float* out = (float*)d_out;

    static int smem_set = 0;
    if (!smem_set) {
        cudaFuncSetAttribute(k_loop, cudaFuncAttributeMaxDynamicSharedMemorySize,
                             SMEM_BYTES);
        smem_set = 1;
    }

    k_init_a<<<592, 256>>>();                          // launch 1
    k_init_b<<<128, 256>>>();                          // launch 2
    k_init_c<<<1, 32>>>();                             // launch 3
    k_loop<<<GRID, NTHR, SMEM_BYTES>>>(pic, W0, H0);   // launch 4 <- ncu slot
    k_hsum<<<256, 256>>>();
    k_sel1<<<1, 1024>>>();
    k_hist2<<<592, 256>>>();
    k_sel2<<<1, 1024>>>(Ht);
    k_final<<<592, 256>>>(Wt, out);
}

// round 15
// speedup vs baseline: 3.0365x; 1.0283x over previous
#include <cuda_runtime.h>
#include <math.h>
#include <stdint.h>

// ---------------------------------------------------------------------------
// HE_ColorNormalization, SMEM-resident persistent NMF, f32x2 24-warp sweep.
//   d_in[0] pic float32 (3,1024,1024) | d_in[1] W_target (3,4) | d_in[2] Ht_RM ()
//   d_in[3] W0 (N,4) | d_in[4] H0 (3,4)    Output: float32 (3,1024,1024)
// 148 CTAs x 768 thr (24 warps/SM, 85-reg budget); Wc + V in smem (215KB).
// Rank-packed fma.rn.f32x2 for num/den/accA; scalar Gram accumulation (regs).
// ---------------------------------------------------------------------------

#define N_PIX    1048576
#define N_ITERS  100
#define EPSF     1e-8f
#define GRID     148
#define NTHR     768
#define PPC      7086                    // pixels owned per CTA
#define KMAX     10
#define PPC_PAD  (KMAX * NTHR)           // 7680, zero-padded tail
#define TOTAL    (4 * N_PIX)
#define RANK0    4152359u                // floor(0.99*(TOTAL-1))
#define RANK1    4152360u
#define HREP     16
#define SMEM_BYTES (PPC_PAD * 28)        // 215040 bytes

typedef unsigned long long u64;

__device__ __forceinline__ u64 pk2(float lo, float hi) {
    u64 r; asm("mov.b64 %0, {%1, %2};" : "=l"(r) : "f"(lo), "f"(hi)); return r;
}
__device__ __forceinline__ void upk2(u64 v, float& lo, float& hi) {
    asm("mov.b64 {%0, %1}, %2;" : "=f"(lo), "=f"(hi) : "l"(v));
}
__device__ __forceinline__ u64 fma2_(u64 a, u64 b, u64 c) {
    u64 d; asm("fma.rn.f32x2 %0, %1, %2, %3;" : "=l"(d) : "l"(a), "l"(b), "l"(c)); return d;
}
__device__ __forceinline__ u64 mul2_(u64 a, u64 b) {
    u64 d; asm("mul.rn.f32x2 %0, %1, %2;" : "=l"(d) : "l"(a), "l"(b)); return d;
}

// Scratch (static device globals: no allocation allowed)
__device__ float4   g_Wc[N_PIX];
__device__ float    g_part[2][22][GRID];
__device__ unsigned g_arrive;
__device__ unsigned g_hist1[HREP * 65536];
__device__ unsigned g_hsum[65536];
__device__ unsigned g_hist2a[65536];
__device__ unsigned g_hist2b[65536];
__device__ unsigned g_bA, g_bB, g_cumA, g_cumB;
__device__ float    g_scale;

__device__ __forceinline__ float od_clip(float x) {
    x = fminf(fmaxf(x, 0.01f), 0.99f);
    return -__logf(x);
}

// --------------------------------------------------------------------------
__global__ void k_init_a() {
    int i = blockIdx.x * blockDim.x + threadIdx.x;
    int stride = gridDim.x * blockDim.x;
    uint4 z = make_uint4(0u, 0u, 0u, 0u);
    uint4* h1 = (uint4*)g_hist1;
    for (int h = i; h < HREP * 65536 / 4; h += stride) h1[h] = z;
}
__global__ void k_init_b() {
    int i = blockIdx.x * blockDim.x + threadIdx.x;
    int stride = gridDim.x * blockDim.x;
    uint4 z = make_uint4(0u, 0u, 0u, 0u);
    uint4* h2a = (uint4*)g_hist2a;
    uint4* h2b = (uint4*)g_hist2b;
    for (int h = i; h < 65536 / 4; h += stride) { h2a[h] = z; h2b[h] = z; }
}
__global__ void k_init_c() {
    if (threadIdx.x == 0 && blockIdx.x == 0) g_arrive = 0u;
}

// --------------------------------------------------------------------------
__global__ __launch_bounds__(NTHR, 1) void k_loop(const float* __restrict__ pic,
                                                  const float* __restrict__ W0,
                                                  const float* __restrict__ H0) {
    extern __shared__ float smem_dyn[];
    float4* swc = (float4*)smem_dyn;            // [PPC_PAD]
    float*  sv0 = (float*)(swc + PPC_PAD);      // [PPC_PAD]
    float*  sv1 = sv0 + PPC_PAD;
    float*  sv2 = sv1 + PPC_PAD;

    __shared__ float sHd[12];
    __shared__ float red[NTHR / 32][22];
    __shared__ float tot[22];

    const int tid  = threadIdx.x;
    const int cta  = blockIdx.x;
    const int warp = tid >> 5, lane = tid & 31;
    const int base = cta * PPC;

    if (tid < 12) sHd[tid] = H0[tid];

    // Prologue: load slab (zero the pad so it contributes nothing)
    const float4* w04 = (const float4*)W0;
    for (int l = tid; l < PPC_PAD; l += NTHR) {
        int p = base + l;
        bool ok = (l < PPC) && (p < N_PIX);
        if (ok) {
            swc[l] = w04[p];
            sv0[l] = od_clip(pic[p]);
            sv1[l] = od_clip(pic[N_PIX + p]);
            sv2[l] = od_clip(pic[2 * N_PIX + p]);
        } else {
            swc[l] = make_float4(0.f, 0.f, 0.f, 0.f);
            sv0[l] = 0.f; sv1[l] = 0.f; sv2[l] = 0.f;
        }
    }
    __syncthreads();

    unsigned* hist = &g_hist1[(cta & (HREP - 1)) * 65536];

    for (int iter = 0; iter < N_ITERS; iter++) {
        float hd[12];
#pragma unroll
        for (int t = 0; t < 12; t++) hd[t] = sHd[t];

        // Gram G[k][j] = sum_c hd[c][k]*hd[c][j], packed as rank-pair columns
        u64 hd2[3][2], G2[4][2];
#pragma unroll
        for (int c = 0; c < 3; c++) {
            hd2[c][0] = pk2(hd[c*4+0], hd[c*4+1]);
            hd2[c][1] = pk2(hd[c*4+2], hd[c*4+3]);
        }
#pragma unroll
        for (int k = 0; k < 4; k++) {
            float gk0 = hd[k]*hd[0] + hd[4+k]*hd[4+0] + hd[8+k]*hd[8+0];
            float gk1 = hd[k]*hd[1] + hd[4+k]*hd[4+1] + hd[8+k]*hd[8+1];
            float gk2 = hd[k]*hd[2] + hd[4+k]*hd[4+2] + hd[8+k]*hd[8+2];
            float gk3 = hd[k]*hd[3] + hd[4+k]*hd[4+3] + hd[8+k]*hd[8+3];
            G2[k][0] = pk2(gk0, gk1);
            G2[k][1] = pk2(gk2, gk3);
        }
        const u64 eps2 = pk2(EPSF, EPSF);

        u64 aA[3][2];
        float aB[10];
#pragma unroll
        for (int c = 0; c < 3; c++) { aA[c][0] = 0ull; aA[c][1] = 0ull; }
#pragma unroll
        for (int t = 0; t < 10; t++) aB[t] = 0.0f;

        const bool last = (iter == N_ITERS - 1);

#pragma unroll
        for (int k = 0; k < KMAX; k++) {
            const int l = tid + k * NTHR;

            float4 w = swc[l];
            float v0 = sv0[l], v1 = sv1[l], v2 = sv2[l];

            u64 vb0 = pk2(v0, v0), vb1 = pk2(v1, v1), vb2 = pk2(v2, v2);
            u64 n0 = fma2_(vb0, hd2[0][0], fma2_(vb1, hd2[1][0], mul2_(vb2, hd2[2][0])));
            u64 n1 = fma2_(vb0, hd2[0][1], fma2_(vb1, hd2[1][1], mul2_(vb2, hd2[2][1])));

            u64 wb0 = pk2(w.x, w.x), wb1 = pk2(w.y, w.y);
            u64 wb2 = pk2(w.z, w.z), wb3 = pk2(w.w, w.w);
            u64 d0 = fma2_(wb0, G2[0][0], fma2_(wb1, G2[1][0],
                     fma2_(wb2, G2[2][0], fma2_(wb3, G2[3][0], eps2))));
            u64 d1 = fma2_(wb0, G2[0][1], fma2_(wb1, G2[1][1],
                     fma2_(wb2, G2[2][1], fma2_(wb3, G2[3][1], eps2))));

            float num0, num1, num2, num3, den0, den1, den2, den3;
            upk2(n0, num0, num1); upk2(n1, num2, num3);
            upk2(d0, den0, den1); upk2(d1, den2, den3);

            float nw0 = w.x * __fdividef(num0, den0);
            float nw1 = w.y * __fdividef(num1, den1);
            float nw2 = w.z * __fdividef(num2, den2);
            float nw3 = w.w * __fdividef(num3, den3);
            swc[l] = make_float4(nw0, nw1, nw2, nw3);

            // A = V @ nw  (packed, 6 fma2)
            u64 nwp0 = pk2(nw0, nw1), nwp1 = pk2(nw2, nw3);
            aA[0][0] = fma2_(vb0, nwp0, aA[0][0]); aA[0][1] = fma2_(vb0, nwp1, aA[0][1]);
            aA[1][0] = fma2_(vb1, nwp0, aA[1][0]); aA[1][1] = fma2_(vb1, nwp1, aA[1][1]);
            aA[2][0] = fma2_(vb2, nwp0, aA[2][0]); aA[2][1] = fma2_(vb2, nwp1, aA[2][1]);

            // B = nw (x) nw, symmetric 10 (scalar: saves regs + broadcast MOVs)
            aB[0] += nw0*nw0; aB[1] += nw0*nw1; aB[2] += nw0*nw2; aB[3] += nw0*nw3;
            aB[4] += nw1*nw1; aB[5] += nw1*nw2; aB[6] += nw1*nw3;
            aB[7] += nw2*nw2; aB[8] += nw2*nw3; aB[9] += nw3*nw3;

            if (last) {
                int p = base + l;
                if (l < PPC && p < N_PIX) {
                    g_Wc[p] = make_float4(nw0, nw1, nw2, nw3);
                    atomicAdd(&hist[__float_as_uint(nw0) >> 16], 1u);
                    atomicAdd(&hist[__float_as_uint(nw1) >> 16], 1u);
                    atomicAdd(&hist[__float_as_uint(nw2) >> 16], 1u);
                    atomicAdd(&hist[__float_as_uint(nw3) >> 16], 1u);
                }
            }
        }

        if (last) break;

        float acc[22];
        upk2(aA[0][0], acc[0],  acc[1]);  upk2(aA[0][1], acc[2],  acc[3]);
        upk2(aA[1][0], acc[4],  acc[5]);  upk2(aA[1][1], acc[6],  acc[7]);
        upk2(aA[2][0], acc[8],  acc[9]);  upk2(aA[2][1], acc[10], acc[11]);
#pragma unroll
        for (int t = 0; t < 10; t++) acc[12 + t] = aB[t];

        // CTA reduction
#pragma unroll
        for (int t = 0; t < 22; t++)
#pragma unroll
            for (int off = 16; off > 0; off >>= 1)
                acc[t] += __shfl_down_sync(0xFFFFFFFFu, acc[t], off);
        if (lane == 0) {
#pragma unroll
            for (int t = 0; t < 22; t++) red[warp][t] = acc[t];
        }
        __syncthreads();
        if (tid < 22) {
            float s = 0.0f;
#pragma unroll
            for (int w = 0; w < NTHR / 32; w++) s += red[w][tid];
            g_part[iter & 1][tid][cta] = s;
        }
        __syncthreads();

        // grid barrier (atomicAdd + volatile spin; reset each replay by k_init_c)
        if (tid == 0) {
            __threadfence();
            atomicAdd(&g_arrive, 1u);
            const unsigned target = (unsigned)(iter + 1) * (unsigned)GRID;
            const volatile unsigned* va = &g_arrive;
            while (*va < target) __nanosleep(32);
            __threadfence();
        }
        __syncthreads();

        // all CTAs reduce partials in fixed order (deterministic)
        for (int v = warp; v < 22; v += NTHR / 32) {
            float s = 0.0f;
            for (int b = lane; b < GRID; b += 32) s += g_part[iter & 1][v][b];
#pragma unroll
            for (int off = 16; off > 0; off >>= 1)
                s += __shfl_down_sync(0xFFFFFFFFu, s, off);
            if (lane == 0) tot[v] = s;
        }
        __syncthreads();

        // parallel Hd update: 12 threads, all operands via SHARED memory
        if (tid < 32) {
            float nv = 0.0f;
            if (tid < 12) {
                int c = tid >> 2, j = tid & 3;
                float den = EPSF;
#pragma unroll
                for (int k = 0; k < 4; k++) {
                    int a = k < j ? k : j;
                    int b = k < j ? j : k;
                    int idx = a * 4 - ((a * (a + 1)) >> 1) + b;   // sym(4) packed
                    den += sHd[c * 4 + k] * tot[12 + idx];
                }
                nv = sHd[tid] * __fdividef(tot[c * 4 + j], den);
            }
            __syncwarp();
            if (tid < 12) sHd[tid] = nv;
        }
        __syncthreads();
    }
}

// ---------------------------------------------------------------------------
// Pre-sum the HREP histogram replicas (full grid) so k_sel1 reads 256KB once.
__global__ void k_hsum() {
    int bin = blockIdx.x * blockDim.x + threadIdx.x;
    if (bin < 65536) {
        unsigned s = 0;
#pragma unroll
        for (int r = 0; r < HREP; r++) s += g_hist1[r * 65536 + bin];
        g_hsum[bin] = s;
    }
}

__global__ void k_sel1() {
    __shared__ unsigned chunk[1024];
    int tid = threadIdx.x;
    unsigned s = 0;
    for (int k = 0; k < 64; k++) s += g_hsum[tid * 64 + k];
    chunk[tid] = s;
    __syncthreads();
    if (tid == 0) {
        unsigned run = 0;
        for (int i = 0; i < 1024; i++) { unsigned c = chunk[i]; chunk[i] = run; run += c; }
    }
    __syncthreads();
    unsigned c = chunk[tid];
    for (int k = 0; k < 64; k++) {
        unsigned bin = tid * 64 + k;
        unsigned h = g_hsum[bin];
        if (RANK0 >= c && RANK0 < c + h) { g_bA = bin; g_cumA = c; }
        if (RANK1 >= c && RANK1 < c + h) { g_bB = bin; g_cumB = c; }
        c += h;
    }
}

__global__ void k_hist2() {
    unsigned bA = g_bA, bB = g_bB;
    const uint4* p = (const uint4*)g_Wc;
    int i = blockIdx.x * blockDim.x + threadIdx.x;
    int stride = gridDim.x * blockDim.x;
    for (; i < N_PIX; i += stride) {
        uint4 u = p[i];
        unsigned h0 = u.x >> 16, h1 = u.y >> 16, h2 = u.z >> 16, h3 = u.w >> 16;
        if (h0 == bA) atomicAdd(&g_hist2a[u.x & 0xFFFFu], 1u);
        if (h0 == bB) atomicAdd(&g_hist2b[u.x & 0xFFFFu], 1u);
        if (h1 == bA) atomicAdd(&g_hist2a[u.y & 0xFFFFu], 1u);
        if (h1 == bB) atomicAdd(&g_hist2b[u.y & 0xFFFFu], 1u);
        if (h2 == bA) atomicAdd(&g_hist2a[u.z & 0xFFFFu], 1u);
        if (h2 == bB) atomicAdd(&g_hist2b[u.z & 0xFFFFu], 1u);
        if (h3 == bA) atomicAdd(&g_hist2a[u.w & 0xFFFFu], 1u);
        if (h3 == bB) atomicAdd(&g_hist2b[u.w & 0xFFFFu], 1u);
    }
}

__device__ __forceinline__ void select_low(const unsigned* __restrict__ hist,
                                           unsigned rank, unsigned hi_bits,
                                           unsigned* chunk, float* out_val) {
    int tid = threadIdx.x;
    unsigned s = 0;
    for (int k = 0; k < 64; k++) s += hist[tid * 64 + k];
    chunk[tid] = s;
    __syncthreads();
    if (tid == 0) {
        unsigned run = 0;
        for (int i = 0; i < 1024; i++) { unsigned c = chunk[i]; chunk[i] = run; run += c; }
    }
    __syncthreads();
    unsigned c = chunk[tid];
    for (int k = 0; k < 64; k++) {
        unsigned h = hist[tid * 64 + k];
        if (rank >= c && rank < c + h)
            *out_val = __uint_as_float((hi_bits << 16) | (unsigned)(tid * 64 + k));
        c += h;
    }
    __syncthreads();
}

__global__ void k_sel2(const float* __restrict__ HtRM) {
    __shared__ unsigned chunk[1024];
    __shared__ float vsh[2];
    select_low(g_hist2a, RANK0 - g_cumA, g_bA, chunk, &vsh[0]);
    select_low(g_hist2b, RANK1 - g_cumB, g_bB, chunk, &vsh[1]);
    if (threadIdx.x == 0) {
        double pos = 0.99 * (double)(TOTAL - 1);
        double fr  = pos - floor(pos);
        double q = (double)vsh[0] + fr * ((double)vsh[1] - (double)vsh[0]);
        g_scale = HtRM[0] / (float)q;
    }
}

// ---------------------------------------------------------------------------
__global__ void k_final(const float* __restrict__ Wt, float* __restrict__ out) {
    __shared__ float sw[12];
    if (threadIdx.x < 12) sw[threadIdx.x] = Wt[threadIdx.x];
    __syncthreads();
    float wt[12];
#pragma unroll
    for (int t = 0; t < 12; t++) wt[t] = sw[t];
    float sc = g_scale;
    const int NG = N_PIX / 4;
    float4* out4 = (float4*)out;
    int i = blockIdx.x * blockDim.x + threadIdx.x;
    int stride = gridDim.x * blockDim.x;
    for (int g = i; g < NG; g += stride) {
        float4 cc[4];
#pragma unroll
        for (int q = 0; q < 4; q++) {
            float4 c4 = g_Wc[4 * g + q];
            cc[q] = make_float4(c4.x * sc, c4.y * sc, c4.z * sc, c4.w * sc);
        }
#pragma unroll
        for (int c = 0; c < 3; c++) {
            float4 o;
            float* op = &o.x;
#pragma unroll
            for (int q = 0; q < 4; q++) {
                float t = wt[c*4+0]*cc[q].x + wt[c*4+1]*cc[q].y
                        + wt[c*4+2]*cc[q].z + wt[c*4+3]*cc[q].w;
                float e = __expf(-t);
                op[q] = fminf(fmaxf(e, 0.0f), 1.0f);
            }
            out4[c * NG + g] = o;
        }
    }
}

// ---------------------------------------------------------------------------
extern "C" void kernel_launch(void* const* d_in, const int* in_sizes, int n_in,
                              void* d_out, int out_size) {
    const float* pic = (const float*)d_in[0];
    const float* Wt  = (const float*)d_in[1];
    const float* Ht  = (const float*)d_in[2];
    const float* W0  = (const float*)d_in[3];
    const float* H0  = (const float*)d_in[4];
    float* out = (float*)d_out;

    static int smem_set = 0;
    if (!smem_set) {
        cudaFuncSetAttribute(k_loop, cudaFuncAttributeMaxDynamicSharedMemorySize,
                             SMEM_BYTES);
        smem_set = 1;
    }

    k_init_a<<<592, 256>>>();                          // launch 1
    k_init_b<<<128, 256>>>();                          // launch 2
    k_init_c<<<1, 32>>>();                             // launch 3
    k_loop<<<GRID, NTHR, SMEM_BYTES>>>(pic, W0, H0);   // launch 4 <- ncu slot
    k_hsum<<<256, 256>>>();
    k_sel1<<<1, 1024>>>();
    k_hist2<<<592, 256>>>();
    k_sel2<<<1, 1024>>>(Ht);
    k_final<<<592, 256>>>(Wt, out);
}